// round 9
// baseline (speedup 1.0000x reference)
#include <cuda_runtime.h>
#include <cuda_fp16.h>
#include <cuda_fp8.h>
#include <math.h>

#define N_WORDS 100000
#define N_SAMPLES 65536
#define KNEG 10
#define DIM 128
#define WARPS_PER_BLOCK 8
#define THREADS (WARPS_PER_BLOCK * 32)
#define SAMPLES_PER_WARP 4
#define SAMPLES_PER_BLOCK (WARPS_PER_BLOCK * SAMPLES_PER_WARP)   // 32
#define NBLOCKS (N_SAMPLES / SAMPLES_PER_BLOCK)                  // 2048

// fp8(e4m3) copy of W_out, rebuilt every launch (12.8 MB scratch).
// Row layout PERMUTED: row r, uint4 #gl dword #j = elements [32j+4gl .. +4).
__device__ uint4         g_wout_f8[(size_t)N_WORDS * 8];
__device__ float         g_acc;      // zero at load; self-resets each run
__device__ unsigned int  g_count;    // arrival counter; self-resets each run

// fast log-sigmoid: min(x,0) - log(1 + exp(-|x|)), MUFU-based
__device__ __forceinline__ float log_sigmoid(float x) {
    float t = __expf(-fabsf(x));
    return fminf(x, 0.0f) - __logf(1.0f + t);
}

__device__ __forceinline__ float group8_sum(float v) {
    v += __shfl_xor_sync(0xFFFFFFFFu, v, 1);
    v += __shfl_xor_sync(0xFFFFFFFFu, v, 2);
    v += __shfl_xor_sync(0xFFFFFFFFu, v, 4);
    return v;
}

__device__ __forceinline__ float warp_sum(float v) {
    v += __shfl_xor_sync(0xFFFFFFFFu, v, 16);
    v += __shfl_xor_sync(0xFFFFFFFFu, v, 8);
    v += __shfl_xor_sync(0xFFFFFFFFu, v, 4);
    v += __shfl_xor_sync(0xFFFFFFFFu, v, 2);
    v += __shfl_xor_sync(0xFFFFFFFFu, v, 1);
    return v;
}

// Multi-value butterfly: 8 partial sums across an aligned 8-lane group.
// Stage order s=4,2,1 so offset 4<->bit2, 2<->bit1, 1<->bit0:
// on return lane gl holds the COMPLETE sum of value index gl (identity map).
__device__ __forceinline__ float multi_reduce8(float* v, int gl) {
    int nv = 8;
#pragma unroll
    for (int s = 4; s >= 1; s >>= 1) {
        nv >>= 1;
#pragma unroll
        for (int i = 0; i < nv; i++) {
            const bool hi = (gl & s) != 0;
            float send  = hi ? v[i] : v[i + nv];
            float other = __shfl_xor_sync(0xFFFFFFFFu, send, s);
            v[i] = (hi ? v[i + nv] : v[i]) + other;
        }
    }
    return v[0];
}

__device__ __forceinline__ __half2 fp8x2_to_h2(unsigned short s) {
    __half2_raw r = __nv_cvt_fp8x2_to_halfraw2((__nv_fp8x2_storage_t)s, __NV_E4M3);
    return *reinterpret_cast<__half2*>(&r);
}

// ---- Kernel 1: W_out fp32 -> fp8 e4m3, permuted pack (8 lanes per row) ----
#define CONV_THREADS 256
#define CONV_BLOCKS ((N_WORDS * 8) / CONV_THREADS)   // 3125

__global__ void __launch_bounds__(CONV_THREADS)
convert_wout_kernel(const float* __restrict__ W_out) {
    const int t   = blockIdx.x * CONV_THREADS + threadIdx.x;
    const int row = t >> 3;
    const int gl  = t & 7;
    const float4* src = reinterpret_cast<const float4*>(W_out + (size_t)row * DIM);

    uint4 o;
    unsigned int* od = reinterpret_cast<unsigned int*>(&o);
#pragma unroll
    for (int j = 0; j < 4; j++) {
        float4 f = src[8 * j + gl];       // coalesced 128B per load across group
        unsigned short lo = (unsigned short)
            __nv_cvt_float2_to_fp8x2(make_float2(f.x, f.y), __NV_SATFINITE, __NV_E4M3);
        unsigned short hi = (unsigned short)
            __nv_cvt_float2_to_fp8x2(make_float2(f.z, f.w), __NV_SATFINITE, __NV_E4M3);
        od[j] = (unsigned int)lo | ((unsigned int)hi << 16);
    }
    g_wout_f8[(size_t)row * 8 + gl] = o;
}

// dot of lane's 16 a-halves (ah[8] half2) with one fp8 uint4 (16 weights)
__device__ __forceinline__ float dot16_f8(const __half2* ah, const uint4& u) {
    const unsigned int* ud = reinterpret_cast<const unsigned int*>(&u);
    __half2 acc0 = __float2half2_rn(0.0f);
    __half2 acc1 = __float2half2_rn(0.0f);
#pragma unroll
    for (int j = 0; j < 4; j++) {
        unsigned int d = ud[j];
        __half2 w0 = fp8x2_to_h2((unsigned short)(d & 0xFFFFu));
        __half2 w1 = fp8x2_to_h2((unsigned short)(d >> 16));
        acc0 = __hfma2(ah[2 * j + 0], w0, acc0);
        acc1 = __hfma2(ah[2 * j + 1], w1, acc1);
    }
    float2 f0 = __half22float2(acc0);
    float2 f1 = __half22float2(acc1);
    return (f0.x + f0.y) + (f1.x + f1.y);
}

// ---- Kernel 2: loss ----
__global__ void __launch_bounds__(THREADS)
skipgram_loss_kernel(const int* __restrict__ input_idx,
                     const int* __restrict__ output_idx,
                     const int* __restrict__ neg_idx,
                     const float* __restrict__ W_in,
                     float* __restrict__ out) {
    const int tid  = threadIdx.x;
    const int warp = tid >> 5;
    const int lane = tid & 31;
    const int grp  = lane >> 3;          // 0..3: sample slot within warp
    const int gl   = lane & 7;           // lane within 8-lane group
    const int sloc = warp * SAMPLES_PER_WARP + grp;
    const int n    = blockIdx.x * SAMPLES_PER_BLOCK + sloc;

    // scalar index loads (registers)
    const int i_in  = input_idx[n];
    const int i_out = output_idx[n];
    const int* nrow = neg_idx + (size_t)n * KNEG;
    int nidx[KNEG];
#pragma unroll
    for (int k = 0; k < KNEG; k++) nidx[k] = nrow[k];

    // input vector: float4 at 8j+gl (coalesced), converted to half2[8]
    const float4* in_row = reinterpret_cast<const float4*>(
        W_in + (size_t)i_in * DIM);
    __half2 ah[8];
#pragma unroll
    for (int j = 0; j < 4; j++) {
        float4 f = in_row[8 * j + gl];
        ah[2 * j + 0] = __floats2half2_rn(f.x, f.y);
        ah[2 * j + 1] = __floats2half2_rn(f.z, f.w);
    }

    // 11 dot partials, sign folded: p[0]=+pos, p[1..7]=-neg[0..6], q[0..2]=-neg[7..9]
    float p[8], q[8];
    p[0] = dot16_f8(ah, g_wout_f8[(size_t)i_out * 8 + gl]);
#pragma unroll
    for (int k = 0; k < 7; k++) {
        uint4 u = g_wout_f8[(size_t)nidx[k] * 8 + gl];
        p[k + 1] = -dot16_f8(ah, u);
    }
#pragma unroll
    for (int k = 0; k < 3; k++) {
        uint4 u = g_wout_f8[(size_t)nidx[7 + k] * 8 + gl];
        q[k] = -dot16_f8(ah, u);
    }
#pragma unroll
    for (int k = 3; k < 8; k++) q[k] = 0.0f;

    // transpose-reduce: lane gl gets complete dot #gl of each batch
    float dA = multi_reduce8(p, gl);
    float dB = multi_reduce8(q, gl);

    // one log-sigmoid per lane per batch; mask padding lanes of batch B
    float lp = log_sigmoid(dA) + (gl < 3 ? log_sigmoid(dB) : 0.0f);
    // sum the 11 terms back across the group
    float loss = group8_sum(lp);

    // block reduce + global accumulate (last block finalizes + resets)
    __shared__ float s[SAMPLES_PER_BLOCK];
    if (gl == 0) s[sloc] = loss;
    __syncthreads();
    if (warp == 0) {
        float v = s[lane];               // SAMPLES_PER_BLOCK == 32 exactly
        v = warp_sum(v);
        if (lane == 0) {
            atomicAdd(&g_acc, v);
            __threadfence();
            unsigned int arrived = atomicAdd(&g_count, 1u);
            if (arrived == NBLOCKS - 1) {
                __threadfence();
                float total = atomicExch(&g_acc, 0.0f);   // read + reset
                out[0] = total * (1.0f / (float)N_SAMPLES);
                g_count = 0u;                              // reset for replay
                __threadfence();
            }
        }
    }
}

extern "C" void kernel_launch(void* const* d_in, const int* in_sizes, int n_in,
                              void* d_out, int out_size) {
    const int*   input_idx  = (const int*)d_in[0];
    const int*   output_idx = (const int*)d_in[1];
    const int*   neg_idx    = (const int*)d_in[2];
    const float* W_in       = (const float*)d_in[3];
    const float* W_out      = (const float*)d_in[4];
    float*       out        = (float*)d_out;

    convert_wout_kernel<<<CONV_BLOCKS, CONV_THREADS>>>(W_out);
    skipgram_loss_kernel<<<NBLOCKS, THREADS>>>(input_idx, output_idx, neg_idx,
                                               W_in, out);
}

// round 10
// speedup vs baseline: 1.4391x; 1.4391x over previous
#include <cuda_runtime.h>
#include <cuda_fp16.h>
#include <cuda_fp8.h>
#include <math.h>

#define N_WORDS 100000
#define N_SAMPLES 65536
#define KNEG 10
#define DIM 128
#define WARPS_PER_BLOCK 8
#define THREADS (WARPS_PER_BLOCK * 32)
#define SAMPLES_PER_WARP 8
#define SAMPLES_PER_BLOCK (WARPS_PER_BLOCK * SAMPLES_PER_WARP)   // 64
#define NBLOCKS (N_SAMPLES / SAMPLES_PER_BLOCK)                  // 1024

// fp8(e4m3) copy of W_out, rebuilt every launch (12.8 MB scratch).
// Row layout PERMUTED: row r, uint4 #u dword #j = elements [32j+4u .. +4).
__device__ uint4         g_wout_f8[(size_t)N_WORDS * 8];
__device__ float         g_acc;      // zero at load; self-resets each run
__device__ unsigned int  g_count;    // arrival counter; self-resets each run

// fast log-sigmoid: min(x,0) - log(1 + exp(-|x|)), MUFU-based
__device__ __forceinline__ float log_sigmoid(float x) {
    float t = __expf(-fabsf(x));
    return fminf(x, 0.0f) - __logf(1.0f + t);
}

// sum across an aligned 4-lane group (replicated result)
__device__ __forceinline__ float group4_sum(float v) {
    v += __shfl_xor_sync(0xFFFFFFFFu, v, 1);
    v += __shfl_xor_sync(0xFFFFFFFFu, v, 2);
    return v;
}

__device__ __forceinline__ float warp_sum(float v) {
    v += __shfl_xor_sync(0xFFFFFFFFu, v, 16);
    v += __shfl_xor_sync(0xFFFFFFFFu, v, 8);
    v += __shfl_xor_sync(0xFFFFFFFFu, v, 4);
    v += __shfl_xor_sync(0xFFFFFFFFu, v, 2);
    v += __shfl_xor_sync(0xFFFFFFFFu, v, 1);
    return v;
}

__device__ __forceinline__ __half2 fp8x2_to_h2(unsigned short s) {
    __half2_raw r = __nv_cvt_fp8x2_to_halfraw2((__nv_fp8x2_storage_t)s, __NV_E4M3);
    return *reinterpret_cast<__half2*>(&r);
}

// ---- Kernel 1: W_out fp32 -> fp8 e4m3, permuted pack (8 threads per row) ----
#define CONV_THREADS 256
#define CONV_BLOCKS ((N_WORDS * 8) / CONV_THREADS)   // 3125

__global__ void __launch_bounds__(CONV_THREADS)
convert_wout_kernel(const float* __restrict__ W_out) {
    const int t   = blockIdx.x * CONV_THREADS + threadIdx.x;
    const int row = t >> 3;
    const int u   = t & 7;
    const float4* src = reinterpret_cast<const float4*>(W_out + (size_t)row * DIM);

    uint4 o;
    unsigned int* od = reinterpret_cast<unsigned int*>(&o);
#pragma unroll
    for (int j = 0; j < 4; j++) {
        float4 f = src[8 * j + u];        // coalesced 128B per load across group
        unsigned short lo = (unsigned short)
            __nv_cvt_float2_to_fp8x2(make_float2(f.x, f.y), __NV_SATFINITE, __NV_E4M3);
        unsigned short hi = (unsigned short)
            __nv_cvt_float2_to_fp8x2(make_float2(f.z, f.w), __NV_SATFINITE, __NV_E4M3);
        od[j] = (unsigned int)lo | ((unsigned int)hi << 16);
    }
    g_wout_f8[(size_t)row * 8 + u] = o;
}

// dot of 16 a-halves (ah[8] half2) with one fp8 uint4 (16 weights)
__device__ __forceinline__ float dot16_f8(const __half2* ah, const uint4& u) {
    const unsigned int* ud = reinterpret_cast<const unsigned int*>(&u);
    __half2 acc0 = __float2half2_rn(0.0f);
    __half2 acc1 = __float2half2_rn(0.0f);
#pragma unroll
    for (int j = 0; j < 4; j++) {
        unsigned int d = ud[j];
        __half2 w0 = fp8x2_to_h2((unsigned short)(d & 0xFFFFu));
        __half2 w1 = fp8x2_to_h2((unsigned short)(d >> 16));
        acc0 = __hfma2(ah[2 * j + 0], w0, acc0);
        acc1 = __hfma2(ah[2 * j + 1], w1, acc1);
    }
    float2 f0 = __half22float2(acc0);
    float2 f1 = __half22float2(acc1);
    return (f0.x + f0.y) + (f1.x + f1.y);
}

// ---- Kernel 2: loss — 4 lanes per sample, 8 samples per warp ----
__global__ void __launch_bounds__(THREADS)
skipgram_loss_kernel(const int* __restrict__ input_idx,
                     const int* __restrict__ output_idx,
                     const int* __restrict__ neg_idx,
                     const float* __restrict__ W_in,
                     float* __restrict__ out) {
    const int tid  = threadIdx.x;
    const int warp = tid >> 5;
    const int lane = tid & 31;
    const int grp  = lane >> 2;          // 0..7: sample slot within warp
    const int gl   = lane & 3;           // lane within 4-lane group
    const int sloc = warp * SAMPLES_PER_WARP + grp;   // 0..63
    const int n    = blockIdx.x * SAMPLES_PER_BLOCK + sloc;

    // scalar index loads (registers, broadcast within group)
    const int i_in  = input_idx[n];
    const int i_out = output_idx[n];
    const int* nrow = neg_idx + (size_t)n * KNEG;
    int nidx[KNEG];
#pragma unroll
    for (int k = 0; k < KNEG; k++) nidx[k] = nrow[k];

    // input vector: lane gl covers element blocks matching uint4 #gl and #(gl+4)
    // float4 indices 8j+gl (-> ahA) and 8j+gl+4 (-> ahB), j=0..3; coalesced.
    const float4* in_row = reinterpret_cast<const float4*>(
        W_in + (size_t)i_in * DIM);
    __half2 ahA[8], ahB[8];
#pragma unroll
    for (int j = 0; j < 4; j++) {
        float4 fA = in_row[8 * j + gl];
        float4 fB = in_row[8 * j + gl + 4];
        ahA[2 * j + 0] = __floats2half2_rn(fA.x, fA.y);
        ahA[2 * j + 1] = __floats2half2_rn(fA.z, fA.w);
        ahB[2 * j + 0] = __floats2half2_rn(fB.x, fB.y);
        ahB[2 * j + 1] = __floats2half2_rn(fB.z, fB.w);
    }

    // positive dot: lane loads uint4 gl and gl+4 of the row (32 B)
    float dpos;
    {
        const uint4* r = g_wout_f8 + (size_t)i_out * 8;
        uint4 u0 = r[gl];
        uint4 u1 = r[gl + 4];
        dpos = dot16_f8(ahA, u0) + dot16_f8(ahB, u1);
    }
    dpos = group4_sum(dpos);
    float loss = log_sigmoid(dpos);

    // negatives: flat unrolled, independent chains (ptxas batches loads)
    float dneg[KNEG];
#pragma unroll
    for (int k = 0; k < KNEG; k++) {
        const uint4* r = g_wout_f8 + (size_t)nidx[k] * 8;
        uint4 u0 = r[gl];
        uint4 u1 = r[gl + 4];
        dneg[k] = dot16_f8(ahA, u0) + dot16_f8(ahB, u1);
    }
#pragma unroll
    for (int k = 0; k < KNEG; k++) {
        float d = group4_sum(dneg[k]);
        loss += log_sigmoid(-d);
    }

    // block reduce + global accumulate (last block finalizes + resets)
    __shared__ float s[SAMPLES_PER_BLOCK];
    if (gl == 0) s[sloc] = loss;
    __syncthreads();
    if (warp == 0) {
        float v = s[lane] + s[lane + 32];   // 64 partials -> 32
        v = warp_sum(v);
        if (lane == 0) {
            atomicAdd(&g_acc, v);
            __threadfence();
            unsigned int arrived = atomicAdd(&g_count, 1u);
            if (arrived == NBLOCKS - 1) {
                __threadfence();
                float total = atomicExch(&g_acc, 0.0f);   // read + reset
                out[0] = total * (1.0f / (float)N_SAMPLES);
                g_count = 0u;                              // reset for replay
                __threadfence();
            }
        }
    }
}

extern "C" void kernel_launch(void* const* d_in, const int* in_sizes, int n_in,
                              void* d_out, int out_size) {
    const int*   input_idx  = (const int*)d_in[0];
    const int*   output_idx = (const int*)d_in[1];
    const int*   neg_idx    = (const int*)d_in[2];
    const float* W_in       = (const float*)d_in[3];
    const float* W_out      = (const float*)d_in[4];
    float*       out        = (float*)d_out;

    convert_wout_kernel<<<CONV_BLOCKS, CONV_THREADS>>>(W_out);
    skipgram_loss_kernel<<<NBLOCKS, THREADS>>>(input_idx, output_idx, neg_idx,
                                               W_in, out);
}